// round 15
// baseline (speedup 1.0000x reference)
#include <cuda_runtime.h>
#include <cuda_bf16.h>
#include <math.h>
#include <float.h>
#include <stdint.h>

#define N_NODES 8192
#define HID 256
#define NCLS 5
#define TOPK 11   // K+1
#define SSTR 20   // smem row stride in uint32 (bf16-pair) units
#define NH (N_NODES * HID)
#define XCV_TOT 2560
#define NTILE 64           // N_NODES / 128
#define TSTR 133           // smem fp32 tile row stride (conflict-free both scans)

// dynamic smem per stage (u32): Ahi 0, Alo 2560, Bhi 5120, Blo 7680
#define STG_U32   10240
#define STG_BYTES 40960
#define SMEM_DYN  81920    // also >= 128*133*4 = 68096 for the fp32 tile overlay

// ---------------- scratch (static device globals; no allocation) ----------------
__device__ float g_t[3 * NH];
__device__ float g_h[3 * NH];
__device__ float g_part[3 * 2 * 64 * HID];
__device__ float g_bna[3 * HID];
__device__ float g_bnc[3 * HID];
__device__ int   g_adj_idx[3 * N_NODES * TOPK];
__device__ float g_adj_w[3 * N_NODES * TOPK];
__device__ float g_logits[3 * N_NODES * NCLS];

// per-(row, tile-col) top-11 candidates (46 MB total; reused per modality)
__device__ float g_cand_v[(size_t)N_NODES * NTILE * TOPK];
__device__ int   g_cand_i[(size_t)N_NODES * NTILE * TOPK];

// pre-split bf16 operand buffers
__device__ __nv_bfloat16 g_x_hi[(size_t)N_NODES * XCV_TOT];
__device__ __nv_bfloat16 g_x_lo[(size_t)N_NODES * XCV_TOT];
__device__ __nv_bfloat16 g_ew_hi[HID * XCV_TOT];
__device__ __nv_bfloat16 g_ew_lo[HID * XCV_TOT];
__device__ __nv_bfloat16 g_fn_hi[3 * NH], g_fn_lo[3 * NH];
__device__ __nv_bfloat16 g_ft_hi[3 * NH], g_ft_lo[3 * NH];
__device__ __nv_bfloat16 g_hh_hi[3 * NH], g_hh_lo[3 * NH];
__device__ __nv_bfloat16 g_w1_hi[3 * HID * HID], g_w1_lo[3 * HID * HID];
__device__ __nv_bfloat16 g_w2_hi[3 * HID * HID], g_w2_lo[3 * HID * HID];

__device__ __forceinline__ void dekker(float v, __nv_bfloat16& h, __nv_bfloat16& l)
{
    h = __float2bfloat16(v);
    l = __float2bfloat16(v - __bfloat162float(h));
}

#define MMA_BF16(C, A, B) \
    asm volatile( \
        "mma.sync.aligned.m16n8k16.row.col.f32.bf16.bf16.f32 " \
        "{%0,%1,%2,%3}, {%4,%5,%6,%7}, {%8,%9}, {%0,%1,%2,%3};\n" \
        : "+f"((C)[0]), "+f"((C)[1]), "+f"((C)[2]), "+f"((C)[3]) \
        : "r"((A)[0]), "r"((A)[1]), "r"((A)[2]), "r"((A)[3]), \
          "r"((B)[0]), "r"((B)[1]))

#define LDSM_X4(r0, r1, r2, r3, addr) \
    asm volatile("ldmatrix.sync.aligned.m8n8.x4.shared.b16 {%0,%1,%2,%3}, [%4];" \
        : "=r"(r0), "=r"(r1), "=r"(r2), "=r"(r3) : "r"(addr))

#define CP_ASYNC16(saddr, gptr) \
    asm volatile("cp.async.cg.shared.global [%0], [%1], 16;" :: "r"(saddr), "l"(gptr))
#define CP_COMMIT() asm volatile("cp.async.commit_group;")
#define CP_WAIT(n)  asm volatile("cp.async.wait_group %0;" :: "n"(n))

__device__ __forceinline__ uint32_t smem_u32(const void* p)
{
    return (uint32_t)__cvta_generic_to_shared(p);
}

// ---------------- conversion kernels ---------------------------------------------
__global__ void cvt_pad(const float* __restrict__ src,
                        __nv_bfloat16* __restrict__ dhi,
                        __nv_bfloat16* __restrict__ dlo,
                        int K, int Kp)
{
    const int col = blockIdx.x * 256 + threadIdx.x;
    const int row = blockIdx.y;
    float v = (col < K) ? src[(size_t)row * K + col] : 0.f;
    __nv_bfloat16 h, l; dekker(v, h, l);
    size_t o = (size_t)row * Kp + col;
    dhi[o] = h; dlo[o] = l;
}

__global__ void cvt_transpose(const float* __restrict__ src,
                              __nv_bfloat16* __restrict__ dhi,
                              __nv_bfloat16* __restrict__ dlo,
                              int K, int N, int Kp, int zsSrc, int zsDst)
{
    src += (size_t)blockIdx.z * zsSrc;
    dhi += (size_t)blockIdx.z * zsDst;
    dlo += (size_t)blockIdx.z * zsDst;
    const int k = blockIdx.x * 256 + threadIdx.x;
    const int n = blockIdx.y;
    float v = (k < K) ? src[(size_t)k * N + n] : 0.f;
    __nv_bfloat16 h, l; dekker(v, h, l);
    size_t o = (size_t)n * Kp + k;
    dhi[o] = h; dlo[o] = l;
}

// ---------------- pre-split bf16x3 mma.sync GEMM ---------------------------------
// C = (Ahi+Alo)(Bhi+Blo)^T approx via Dekker (hihi + hilo + lohi), fp32 acc.
// A,B: [*,Kp] bf16 hi/lo row-major, Kp % 32 == 0. cp.async double-buffered.
// SYMM: A==B, lower-tri linear grid; instead of writing C, extract per-row
//       top-11 candidates for this tile (and mirrored tile) into g_cand_*.
template<bool BIAS_RELU, bool SYMM>
__global__ __launch_bounds__(256) void gemm_pre(const __nv_bfloat16* __restrict__ Ahi,
                                                const __nv_bfloat16* __restrict__ Alo,
                                                const __nv_bfloat16* __restrict__ Bhi,
                                                const __nv_bfloat16* __restrict__ Blo,
                                                const float* __restrict__ bias,
                                                float* __restrict__ C,
                                                int M, int N, int Kp,
                                                int zsA, int zsB, int zsBias, int zsC)
{
    extern __shared__ uint32_t smemDyn[];

    Ahi += (size_t)blockIdx.z * zsA;  Alo += (size_t)blockIdx.z * zsA;
    Bhi += (size_t)blockIdx.z * zsB;  Blo += (size_t)blockIdx.z * zsB;
    if (BIAS_RELU) bias += (size_t)blockIdx.z * zsBias;
    if (!SYMM) C += (size_t)blockIdx.z * zsC;

    const int tid  = threadIdx.x;
    const int lane = tid & 31;
    const int warp = tid >> 5;
    const int gid  = lane >> 2;
    const int tig  = lane & 3;
    const int wm   = warp >> 2;
    const int wn   = warp & 3;

    int mo, no;
    bool mirror = false;
    if (SYMM) {
        int t = blockIdx.x;
        int bi = (int)((sqrtf(8.f * (float)t + 1.f) - 1.f) * 0.5f);
        while ((bi + 1) * (bi + 2) / 2 <= t) bi++;
        while (bi * (bi + 1) / 2 > t) bi--;
        int bj = t - bi * (bi + 1) / 2;
        mo = bi * 128; no = bj * 128;
        mirror = (bi != bj);
    } else {
        mo = blockIdx.y * 128;
        no = blockIdx.x * 128;
    }

    float acc[4][4][4];
#pragma unroll
    for (int i = 0; i < 4; i++)
#pragma unroll
        for (int j = 0; j < 4; j++)
#pragma unroll
            for (int q = 0; q < 4; q++) acc[i][j][q] = 0.f;

    const uint32_t aoff = (uint32_t)((wm * 64 + (lane & 7) + ((lane >> 3) & 1) * 8) * (SSTR * 4)
                                     + ((lane >> 4) & 1) * 16);
    const uint32_t boff = (uint32_t)((wn * 32 + (lane & 7) + ((lane >> 4) & 1) * 8) * (SSTR * 4)
                                     + ((lane >> 3) & 1) * 16);
    const uint32_t smemBase = smem_u32(smemDyn);

    auto issueTile = [&](int st, int ko) {
        const uint32_t sb = smemBase + (uint32_t)st * STG_BYTES;
#pragma unroll
        for (int c2 = 0; c2 < 2; c2++) {
            int chunk = c2 * 256 + tid;
            int r = chunk >> 2, q = chunk & 3;
            uint32_t soff = (uint32_t)((r * SSTR + q * 4) * 4);
            const __nv_bfloat16* gah = Ahi + (size_t)(mo + r) * Kp + ko + q * 8;
            const __nv_bfloat16* gal = Alo + (size_t)(mo + r) * Kp + ko + q * 8;
            const __nv_bfloat16* gbh = Bhi + (size_t)(no + r) * Kp + ko + q * 8;
            const __nv_bfloat16* gbl = Blo + (size_t)(no + r) * Kp + ko + q * 8;
            CP_ASYNC16(sb + soff,              gah);
            CP_ASYNC16(sb + 2560u * 4u + soff, gal);
            CP_ASYNC16(sb + 5120u * 4u + soff, gbh);
            CP_ASYNC16(sb + 7680u * 4u + soff, gbl);
        }
        CP_COMMIT();
    };

    issueTile(0, 0);
    int stage = 0;
    for (int ko = 0; ko < Kp; ko += 32) {
        const int kn = ko + 32;
        if (kn < Kp) { issueTile(stage ^ 1, kn); CP_WAIT(1); }
        else         { CP_WAIT(0); }
        __syncthreads();

        const uint32_t sb   = smemBase + (uint32_t)stage * STG_BYTES;
        const uint32_t ahiB = sb + aoff;
        const uint32_t aloB = sb + 2560u * 4u + aoff;
        const uint32_t bhiB = sb + 5120u * 4u + boff;
        const uint32_t bloB = sb + 7680u * 4u + boff;
#pragma unroll
        for (int ks = 0; ks < 2; ks++) {
            const uint32_t kb = (uint32_t)(ks * 32);
            uint32_t bhi[4][2], blo[4][2];
#pragma unroll
            for (int p = 0; p < 2; p++) {
                LDSM_X4(bhi[2 * p][0], bhi[2 * p][1], bhi[2 * p + 1][0], bhi[2 * p + 1][1],
                        bhiB + (uint32_t)(p * 16 * SSTR * 4) + kb);
                LDSM_X4(blo[2 * p][0], blo[2 * p][1], blo[2 * p + 1][0], blo[2 * p + 1][1],
                        bloB + (uint32_t)(p * 16 * SSTR * 4) + kb);
            }
#pragma unroll
            for (int i = 0; i < 4; i++) {
                uint32_t ahi[4], alo[4];
                LDSM_X4(ahi[0], ahi[1], ahi[2], ahi[3],
                        ahiB + (uint32_t)(i * 16 * SSTR * 4) + kb);
                LDSM_X4(alo[0], alo[1], alo[2], alo[3],
                        aloB + (uint32_t)(i * 16 * SSTR * 4) + kb);
#pragma unroll
                for (int j = 0; j < 4; j++) {
                    MMA_BF16(acc[i][j], ahi, bhi[j]);
                    MMA_BF16(acc[i][j], ahi, blo[j]);
                    MMA_BF16(acc[i][j], alo, bhi[j]);
                }
            }
        }
        __syncthreads();
        stage ^= 1;
    }

    if (SYMM) {
        // ---- stage tile into smem (overlay the pipeline buffers; all reads done)
        float* stile = reinterpret_cast<float*>(smemDyn);   // [128][TSTR]
#pragma unroll
        for (int i = 0; i < 4; i++) {
            const int rl = wm * 64 + i * 16 + gid;
#pragma unroll
            for (int j = 0; j < 4; j++) {
                const int cl = wn * 32 + j * 8 + tig * 2;
                stile[rl * TSTR + cl]           = acc[i][j][0];
                stile[rl * TSTR + cl + 1]       = acc[i][j][1];
                stile[(rl + 8) * TSTR + cl]     = acc[i][j][2];
                stile[(rl + 8) * TSTR + cl + 1] = acc[i][j][3];
            }
        }
        __syncthreads();

        float lv[TOPK]; int li[TOPK];
#pragma unroll
        for (int k = 0; k < TOPK; k++) { lv[k] = -FLT_MAX; li[k] = 0x7FFFFFFF; }
        auto insert = [&](float v, int jdx) {
            if (v > lv[TOPK - 1]) {
                lv[TOPK - 1] = v; li[TOPK - 1] = jdx;
#pragma unroll
                for (int k = TOPK - 1; k > 0; k--) {
                    if (lv[k] > lv[k - 1]) {
                        float tv = lv[k]; lv[k] = lv[k - 1]; lv[k - 1] = tv;
                        int   ti = li[k]; li[k] = li[k - 1]; li[k - 1] = ti;
                    } else break;
                }
            }
        };

        if (tid < 128) {
            // row pass: row mo+tid, cols no..no+127 (idx ascending -> strict > OK)
            const float* rowp = stile + tid * TSTR;
            for (int c = 0; c < 128; c++) insert(rowp[c], no + c);
            size_t base = ((size_t)(mo + tid) * NTILE + (no >> 7)) * TOPK;
#pragma unroll
            for (int k = 0; k < TOPK; k++) { g_cand_v[base + k] = lv[k]; g_cand_i[base + k] = li[k]; }
        } else if (mirror) {
            // mirror pass: row no+c over cols mo..mo+127 (tile transposed)
            const int c = tid - 128;
            for (int r = 0; r < 128; r++) insert(stile[r * TSTR + c], mo + r);
            size_t base = ((size_t)(no + c) * NTILE + (mo >> 7)) * TOPK;
#pragma unroll
            for (int k = 0; k < TOPK; k++) { g_cand_v[base + k] = lv[k]; g_cand_i[base + k] = li[k]; }
        }
        return;
    }

    // ---- normal epilogue
#pragma unroll
    for (int i = 0; i < 4; i++) {
        const int r0 = mo + wm * 64 + i * 16 + gid;
#pragma unroll
        for (int j = 0; j < 4; j++) {
            const int c = no + wn * 32 + j * 8 + tig * 2;
            float v0 = acc[i][j][0], v1 = acc[i][j][1];
            float v2 = acc[i][j][2], v3 = acc[i][j][3];
            if (BIAS_RELU) {
                const float b0 = bias[c], b1 = bias[c + 1];
                v0 = fmaxf(v0 + b0, 0.f); v1 = fmaxf(v1 + b1, 0.f);
                v2 = fmaxf(v2 + b0, 0.f); v3 = fmaxf(v3 + b1, 0.f);
            }
            *reinterpret_cast<float2*>(&C[(size_t)r0 * N + c])       = make_float2(v0, v1);
            *reinterpret_cast<float2*>(&C[(size_t)(r0 + 8) * N + c]) = make_float2(v2, v3);
        }
    }
}

// ---------------- BatchNorm stats (two stage, deterministic, z-batched) ----------
__global__ void bn_colpart(void)
{
    const int z = blockIdx.z;
    const float* t = g_t + (size_t)z * NH;
    float* part = g_part + (size_t)z * 2 * 64 * HID;
    const int c = threadIdx.x;
    const int r0 = blockIdx.x * 128;
    float s = 0.f, s2 = 0.f;
    for (int r = r0; r < r0 + 128; r++) {
        float v = t[(size_t)r * HID + c];
        s += v; s2 += v * v;
    }
    part[blockIdx.x * HID + c] = s;
    part[64 * HID + blockIdx.x * HID + c] = s2;
}

__global__ void bn_colfinal(const float* __restrict__ gam, const float* __restrict__ bet)
{
    const int z = blockIdx.z;
    const float* part = g_part + (size_t)z * 2 * 64 * HID;
    const int c = threadIdx.x;
    float s = 0.f, s2 = 0.f;
    for (int b = 0; b < 64; b++) {
        s  += part[b * HID + c];
        s2 += part[64 * HID + b * HID + c];
    }
    const float mu = s * (1.f / N_NODES);
    float var = s2 * (1.f / N_NODES) - mu * mu;
    const float a = gam[z * HID + c] * rsqrtf(var + 1e-5f);
    g_bna[z * HID + c] = a;
    g_bnc[z * HID + c] = bet[z * HID + c] - mu * a;
}

__global__ __launch_bounds__(256) void bn_apply_rownorm(void)
{
    const int z = blockIdx.z;
    const float* t = g_t + (size_t)z * NH;
    __nv_bfloat16* fth = g_ft_hi + (size_t)z * NH;
    __nv_bfloat16* ftl = g_ft_lo + (size_t)z * NH;
    __nv_bfloat16* fnh = g_fn_hi + (size_t)z * NH;
    __nv_bfloat16* fnl = g_fn_lo + (size_t)z * NH;
    const int tid = threadIdx.x;
    const int warp = tid >> 5, lane = tid & 31;
    const int row = blockIdx.x * 8 + warp;
    float v[8];
    float sq = 0.f;
#pragma unroll
    for (int u = 0; u < 8; u++) {
        int c = lane + 32 * u;
        float x = g_bna[z * HID + c] * t[(size_t)row * HID + c] + g_bnc[z * HID + c];
        v[u] = x; sq += x * x;
    }
#pragma unroll
    for (int s = 16; s; s >>= 1) sq += __shfl_xor_sync(0xffffffffu, sq, s);
    const float norm = sqrtf(sq);
    const float inv = 1.f / fmaxf(norm, 1e-12f);
#pragma unroll
    for (int u = 0; u < 8; u++) {
        int c = lane + 32 * u;
        size_t o = (size_t)row * HID + c;
        __nv_bfloat16 h, l;
        dekker(v[u], h, l);          fth[o] = h; ftl[o] = l;
        dekker(v[u] * inv, h, l);    fnh[o] = h; fnl[o] = l;
    }
}

// ---------------- merge candidates -> global top-(K+1) + adjacency ---------------
// Scans 64*11 = 704 tile candidates per row. Generalized lexicographic insert
// (value desc, index asc) makes the per-thread lists exact regardless of scan
// order; the proven tree merge then reproduces the original selection exactly.
__global__ __launch_bounds__(256) void topk_adj(int* __restrict__ aidx,
                                                float* __restrict__ aw)
{
    const int row = blockIdx.x;
    const int tid = threadIdx.x;
    const float* __restrict__ cvg = g_cand_v + (size_t)row * NTILE * TOPK;
    const int*   __restrict__ cig = g_cand_i + (size_t)row * NTILE * TOPK;

    float lv[TOPK]; int li[TOPK];
#pragma unroll
    for (int k = 0; k < TOPK; k++) { lv[k] = -FLT_MAX; li[k] = 0x7FFFFFFF; }

    for (int j = tid; j < NTILE * TOPK; j += 256) {
        float v = cvg[j];
        int   jd = cig[j];
        if (v > lv[TOPK - 1] || (v == lv[TOPK - 1] && jd < li[TOPK - 1])) {
            lv[TOPK - 1] = v; li[TOPK - 1] = jd;
#pragma unroll
            for (int k = TOPK - 1; k > 0; k--) {
                if (lv[k] > lv[k - 1] || (lv[k] == lv[k - 1] && li[k] < li[k - 1])) {
                    float tv = lv[k]; lv[k] = lv[k - 1]; lv[k - 1] = tv;
                    int   ti = li[k]; li[k] = li[k - 1]; li[k - 1] = ti;
                } else break;
            }
        }
    }

    __shared__ float cv[256 * TOPK];
    __shared__ int   ci[256 * TOPK];
#pragma unroll
    for (int k = 0; k < TOPK; k++) { cv[tid * TOPK + k] = lv[k]; ci[tid * TOPK + k] = li[k]; }

    __shared__ float rv[256];
    __shared__ int   ri[256];
    __shared__ float topv[TOPK];
    __shared__ int   topi[TOPK];

    int p = 0;
    for (int r = 0; r < TOPK; r++) {
        float mv = (p < TOPK) ? cv[tid * TOPK + p] : -FLT_MAX;
        int   mj = (p < TOPK) ? ci[tid * TOPK + p] : 0x7FFFFFFF;
        rv[tid] = mv; ri[tid] = mj;
        __syncthreads();
        for (int s = 128; s > 0; s >>= 1) {
            if (tid < s) {
                float ov = rv[tid + s]; int oj = ri[tid + s];
                if (ov > rv[tid] || (ov == rv[tid] && oj < ri[tid])) { rv[tid] = ov; ri[tid] = oj; }
            }
            __syncthreads();
        }
        int bj = ri[0];
        if (tid == 0) { topv[r] = rv[0]; topi[r] = bj; }
        if (mj == bj) p++;           // indices unique across candidates of a row
        __syncthreads();
    }

    if (tid == 0) {
        float diag = 1.0f;
        float wv[TOPK]; int wi[TOPK]; int cnt = 0;
        for (int k = 1; k < TOPK; k++) {
            if (topi[k] == row) diag += topv[k];
            else { wv[cnt] = topv[k]; wi[cnt] = topi[k]; cnt++; }
        }
        float rs = fabsf(diag);
        for (int k = 0; k < cnt; k++) rs += fabsf(wv[k]);
        rs = fmaxf(rs, 1e-12f);
        const float inv = 1.f / rs;
        aidx[row * TOPK + 0] = row;
        aw[row * TOPK + 0]   = diag * inv;
        for (int k = 0; k < cnt; k++) {
            aidx[row * TOPK + 1 + k] = wi[k];
            aw[row * TOPK + 1 + k]   = wv[k] * inv;
        }
        for (int k = cnt; k < TOPK - 1; k++) {
            aidx[row * TOPK + 1 + k] = row;
            aw[row * TOPK + 1 + k]   = 0.f;
        }
    }
}

// ---------------- sparse adj @ t + bias, leaky(0.25); emits h fp32 + bf16 hi/lo --
__global__ void spmm_leaky(const float* __restrict__ t,
                           const float* __restrict__ bias,
                           float* __restrict__ out)
{
    const int z = blockIdx.z;
    const float* tz = t + (size_t)z * NH;
    const float* bz = bias + (size_t)z * HID;
    float* oz = out + (size_t)z * NH;
    __nv_bfloat16* hh = g_hh_hi + (size_t)z * NH;
    __nv_bfloat16* hl = g_hh_lo + (size_t)z * NH;
    const int* ai = g_adj_idx + (size_t)z * N_NODES * TOPK;
    const float* aw = g_adj_w + (size_t)z * N_NODES * TOPK;

    const int row = blockIdx.x;
    const int c = threadIdx.x;
    float acc = bz[c];
#pragma unroll
    for (int k = 0; k < TOPK; k++) {
        int   j = ai[row * TOPK + k];
        float w = aw[row * TOPK + k];
        acc += w * tz[(size_t)j * HID + c];
    }
    float r = (acc >= 0.f) ? acc : 0.25f * acc;
    size_t o = (size_t)row * HID + c;
    oz[o] = r;
    __nv_bfloat16 h, l; dekker(r, h, l);
    hh[o] = h; hl[o] = l;
}

// ---------------- classifier (z-batched) ------------------------------------------
__global__ __launch_bounds__(256) void clf_kernel(const float* __restrict__ h,
                                                  const float* __restrict__ W,
                                                  const float* __restrict__ b)
{
    const int z = blockIdx.z;
    const float* hz = h + (size_t)z * NH;
    const float* Wz = W + (size_t)z * HID * NCLS;
    const float* bz = b + (size_t)z * NCLS;
    float* oz = g_logits + (size_t)z * N_NODES * NCLS;

    __shared__ float Ws[HID * NCLS];
    const int tid = threadIdx.x;
    for (int i = tid; i < HID * NCLS; i += 256) Ws[i] = Wz[i];
    __syncthreads();
    const int warp = tid >> 5, lane = tid & 31;
    const int row = blockIdx.x * 8 + warp;
    float hv[8];
#pragma unroll
    for (int u = 0; u < 8; u++) hv[u] = hz[(size_t)row * HID + lane + 32 * u];
#pragma unroll
    for (int c = 0; c < NCLS; c++) {
        float acc = 0.f;
#pragma unroll
        for (int u = 0; u < 8; u++) acc += hv[u] * Ws[(lane + 32 * u) * NCLS + c];
#pragma unroll
        for (int s = 16; s; s >>= 1) acc += __shfl_down_sync(0xffffffffu, acc, s);
        if (lane == 0) oz[row * NCLS + c] = acc + bz[c];
    }
}

// ---------------- fusion ----------------------------------------------------------
__global__ __launch_bounds__(256) void fusion_kernel(const float* __restrict__ attn,
                                                     const float* __restrict__ f1W,
                                                     const float* __restrict__ f1b,
                                                     const float* __restrict__ f2W,
                                                     const float* __restrict__ f2b,
                                                     float* __restrict__ out)
{
    __shared__ float s1[NCLS * 128];
    __shared__ float s2[128 * NCLS];
    __shared__ float sb1[128];
    __shared__ float sb2[NCLS];
    const int tid = threadIdx.x;
    for (int i = tid; i < NCLS * 128; i += 256) s1[i] = f1W[i];
    for (int i = tid; i < 128 * NCLS; i += 256) s2[i] = f2W[i];
    if (tid < 128) sb1[tid] = f1b[tid];
    if (tid < NCLS) sb2[tid] = f2b[tid];
    __syncthreads();

    const int row = blockIdx.x * 256 + tid;
    const float a0 = attn[0], a1 = attn[1], a2 = attn[2];
    const float m = fmaxf(a0, fmaxf(a1, a2));
    const float e0 = expf(a0 - m), e1 = expf(a1 - m), e2 = expf(a2 - m);
    const float invs = 1.f / (e0 + e1 + e2);
    const float w0 = e0 * invs, w1 = e1 * invs, w2 = e2 * invs;

    float fused[NCLS];
#pragma unroll
    for (int c = 0; c < NCLS; c++) {
        float l0 = g_logits[0 * N_NODES * NCLS + row * NCLS + c];
        float l1 = g_logits[1 * N_NODES * NCLS + row * NCLS + c];
        float l2 = g_logits[2 * N_NODES * NCLS + row * NCLS + c];
        fused[c] = w0 / (1.f + expf(-l0)) + w1 / (1.f + expf(-l1)) + w2 / (1.f + expf(-l2));
    }
    float o[NCLS];
#pragma unroll
    for (int c = 0; c < NCLS; c++) o[c] = sb2[c];
    for (int j = 0; j < 128; j++) {
        float t = sb1[j];
#pragma unroll
        for (int c = 0; c < NCLS; c++) t += fused[c] * s1[c * 128 + j];
        t = (t >= 0.f) ? t : 0.25f * t;
#pragma unroll
        for (int c = 0; c < NCLS; c++) o[c] += t * s2[j * NCLS + c];
    }
#pragma unroll
    for (int c = 0; c < NCLS; c++) out[(size_t)row * NCLS + c] = o[c];
}

// ---------------- host launcher ----------------
extern "C" void kernel_launch(void* const* d_in, const int* in_sizes, int n_in,
                              void* d_out, int out_size)
{
    (void)n_in; (void)out_size;
    const float* x[3]    = {(const float*)d_in[0], (const float*)d_in[1], (const float*)d_in[2]};
    const float* encW[3] = {(const float*)d_in[3], (const float*)d_in[4], (const float*)d_in[5]};
    const float* enc_b = (const float*)d_in[6];
    const float* bn_g  = (const float*)d_in[7];
    const float* bn_b  = (const float*)d_in[8];
    const float* gc1W  = (const float*)d_in[9];
    const float* gc1b  = (const float*)d_in[10];
    const float* gc2W  = (const float*)d_in[11];
    const float* gc2b  = (const float*)d_in[12];
    const float* clfW  = (const float*)d_in[13];
    const float* clfb  = (const float*)d_in[14];
    const float* attn  = (const float*)d_in[15];
    const float* f1W   = (const float*)d_in[16];
    const float* f1b   = (const float*)d_in[17];
    const float* f2W   = (const float*)d_in[18];
    const float* f2b   = (const float*)d_in[19];

    float *p_t, *p_h;
    int   *p_aidx; float *p_aw;
    __nv_bfloat16 *p_xh, *p_xl, *p_ewh, *p_ewl, *p_fnh, *p_fnl, *p_fth, *p_ftl;
    __nv_bfloat16 *p_hhh, *p_hhl, *p_w1h, *p_w1l, *p_w2h, *p_w2l;
    cudaGetSymbolAddress((void**)&p_t,    g_t);
    cudaGetSymbolAddress((void**)&p_h,    g_h);
    cudaGetSymbolAddress((void**)&p_aidx, g_adj_idx);
    cudaGetSymbolAddress((void**)&p_aw,   g_adj_w);
    cudaGetSymbolAddress((void**)&p_xh,   g_x_hi);
    cudaGetSymbolAddress((void**)&p_xl,   g_x_lo);
    cudaGetSymbolAddress((void**)&p_ewh,  g_ew_hi);
    cudaGetSymbolAddress((void**)&p_ewl,  g_ew_lo);
    cudaGetSymbolAddress((void**)&p_fnh,  g_fn_hi);
    cudaGetSymbolAddress((void**)&p_fnl,  g_fn_lo);
    cudaGetSymbolAddress((void**)&p_fth,  g_ft_hi);
    cudaGetSymbolAddress((void**)&p_ftl,  g_ft_lo);
    cudaGetSymbolAddress((void**)&p_hhh,  g_hh_hi);
    cudaGetSymbolAddress((void**)&p_hhl,  g_hh_lo);
    cudaGetSymbolAddress((void**)&p_w1h,  g_w1_hi);
    cudaGetSymbolAddress((void**)&p_w1l,  g_w1_lo);
    cudaGetSymbolAddress((void**)&p_w2h,  g_w2_hi);
    cudaGetSymbolAddress((void**)&p_w2l,  g_w2_lo);

    cudaFuncSetAttribute(gemm_pre<true,  false>,
                         cudaFuncAttributeMaxDynamicSharedMemorySize, SMEM_DYN);
    cudaFuncSetAttribute(gemm_pre<false, true>,
                         cudaFuncAttributeMaxDynamicSharedMemorySize, SMEM_DYN);
    cudaFuncSetAttribute(gemm_pre<false, false>,
                         cudaFuncAttributeMaxDynamicSharedMemorySize, SMEM_DYN);

    const int NSYMM = NTILE * (NTILE + 1) / 2;   // 2080

    int Kp[3], xoff[3], eoff[3];
    int xacc = 0;
    for (int i = 0; i < 3; i++) {
        int K = in_sizes[i] / N_NODES;
        Kp[i] = (K + 31) & ~31;
        xoff[i] = xacc * N_NODES;
        eoff[i] = xacc * HID;
        xacc += Kp[i];
    }

    // ---- pre-split conversions ----
    for (int i = 0; i < 3; i++) {
        int K = in_sizes[i] / N_NODES;
        cvt_pad<<<dim3(Kp[i] / 256, N_NODES), 256>>>(x[i], p_xh + xoff[i], p_xl + xoff[i], K, Kp[i]);
        cvt_transpose<<<dim3(Kp[i] / 256, HID), 256>>>(encW[i], p_ewh + eoff[i], p_ewl + eoff[i],
                                                       K, HID, Kp[i], 0, 0);
    }
    cvt_transpose<<<dim3(1, HID, 3), 256>>>(gc1W, p_w1h, p_w1l, HID, HID, HID,
                                            HID * HID, HID * HID);
    cvt_transpose<<<dim3(1, HID, 3), 256>>>(gc2W, p_w2h, p_w2l, HID, HID, HID,
                                            HID * HID, HID * HID);

    // ---- encoders ----
    for (int i = 0; i < 3; i++) {
        dim3 grid(HID / 128, N_NODES / 128, 1);
        gemm_pre<true, false><<<grid, 256, SMEM_DYN>>>(
            p_xh + xoff[i], p_xl + xoff[i], p_ewh + eoff[i], p_ewl + eoff[i],
            enc_b + i * HID, p_t + (size_t)i * NH,
            N_NODES, HID, Kp[i], 0, 0, 0, 0);
    }

    // ---- batchnorm + rownorm ----
    bn_colpart<<<dim3(64, 1, 3), 256>>>();
    bn_colfinal<<<dim3(1, 1, 3), 256>>>(bn_g, bn_b);
    bn_apply_rownorm<<<dim3(N_NODES / 8, 1, 3), 256>>>();

    // ---- per modality: fused sim+topk-candidates, then merge ----
    for (int i = 0; i < 3; i++) {
        gemm_pre<false, true><<<dim3(NSYMM, 1, 1), 256, SMEM_DYN>>>(
            p_fnh + (size_t)i * NH, p_fnl + (size_t)i * NH,
            p_fnh + (size_t)i * NH, p_fnl + (size_t)i * NH,
            nullptr, nullptr, N_NODES, N_NODES, HID, 0, 0, 0, 0);
        topk_adj<<<N_NODES, 256>>>(p_aidx + (size_t)i * N_NODES * TOPK,
                                   p_aw   + (size_t)i * N_NODES * TOPK);
    }

    // ---- GCN layers (batched z=3) ----
    {
        dim3 grid(HID / 128, N_NODES / 128, 3);
        gemm_pre<false, false><<<grid, 256, SMEM_DYN>>>(
            p_fth, p_ftl, p_w1h, p_w1l, nullptr, p_t,
            N_NODES, HID, HID, NH, HID * HID, 0, NH);
        spmm_leaky<<<dim3(N_NODES, 1, 3), HID>>>(p_t, gc1b, p_h);
        gemm_pre<false, false><<<grid, 256, SMEM_DYN>>>(
            p_hhh, p_hhl, p_w2h, p_w2l, nullptr, p_t,
            N_NODES, HID, HID, NH, HID * HID, 0, NH);
        spmm_leaky<<<dim3(N_NODES, 1, 3), HID>>>(p_t, gc2b, p_h);
    }

    // ---- classifier + fusion ----
    clf_kernel<<<dim3(N_NODES / 8, 1, 3), 256>>>(p_h, clfW, clfb);
    fusion_kernel<<<N_NODES / 256, 256>>>(attn, f1W, f1b, f2W, f2b, (float*)d_out);
}

// round 16
// speedup vs baseline: 1.1126x; 1.1126x over previous
#include <cuda_runtime.h>
#include <math.h>
#include <float.h>
#include <stdint.h>

#define N_NODES 8192
#define HID 256
#define NCLS 5
#define TOPK 11   // K+1
#define SSTR 20   // smem row stride in uint32 (bf16-pair) units; 16 pairs + 4 pad
#define NH (N_NODES * HID)
#define NN ((size_t)N_NODES * N_NODES)

// ---------------- scratch (static device globals; no allocation) ----------------
__device__ float g_sim[3 * NN];                      // 768 MB: one sim per modality
__device__ float g_t[3 * NH];
__device__ float g_feat[3 * NH];
__device__ float g_fn[3 * NH];
__device__ float g_h[3 * NH];
__device__ float g_part[3 * 2 * 64 * HID];
__device__ float g_bna[3 * HID];
__device__ float g_bnc[3 * HID];
__device__ int   g_adj_idx[3 * N_NODES * TOPK];
__device__ float g_adj_w[3 * N_NODES * TOPK];
__device__ float g_logits[3 * N_NODES * NCLS];

// pack two floats to bf16x2 (low = x, high = y), round-to-nearest
__device__ __forceinline__ uint32_t pack_bf16(float x, float y)
{
    uint32_t r;
    asm("cvt.rn.bf16x2.f32 %0, %1, %2;" : "=r"(r) : "f"(y), "f"(x));
    return r;
}
__device__ __forceinline__ float bf16lo_f(uint32_t p) { return __uint_as_float(p << 16); }
__device__ __forceinline__ float bf16hi_f(uint32_t p) { return __uint_as_float(p & 0xFFFF0000u); }

__device__ __forceinline__ void split4(float4 v, uint32_t& h0, uint32_t& h1,
                                       uint32_t& l0, uint32_t& l1)
{
    h0 = pack_bf16(v.x, v.y);
    h1 = pack_bf16(v.z, v.w);
    l0 = pack_bf16(v.x - bf16lo_f(h0), v.y - bf16hi_f(h0));
    l1 = pack_bf16(v.z - bf16lo_f(h1), v.w - bf16hi_f(h1));
}

#define MMA_BF16(C, A, B) \
    asm volatile( \
        "mma.sync.aligned.m16n8k16.row.col.f32.bf16.bf16.f32 " \
        "{%0,%1,%2,%3}, {%4,%5,%6,%7}, {%8,%9}, {%0,%1,%2,%3};\n" \
        : "+f"((C)[0]), "+f"((C)[1]), "+f"((C)[2]), "+f"((C)[3]) \
        : "r"((A)[0]), "r"((A)[1]), "r"((A)[2]), "r"((A)[3]), \
          "r"((B)[0]), "r"((B)[1]))

#define LDSM_X4(r0, r1, r2, r3, addr) \
    asm volatile("ldmatrix.sync.aligned.m8n8.x4.shared.b16 {%0,%1,%2,%3}, [%4];" \
        : "=r"(r0), "=r"(r1), "=r"(r2), "=r"(r3) : "r"(addr))

__device__ __forceinline__ uint32_t smem_u32(const void* p)
{
    return (uint32_t)__cvta_generic_to_shared(p);
}

// ---------------- bf16x3 split-precision tensor-core GEMM ------------------------
// C[M,N] = A[M,K] * op(B) (+bias,+relu).  Dekker split: Ahi*Bhi + Ahi*Blo + Alo*Bhi.
// TRANSB=true : B is [N,K] row-major (C = A * B^T); false: B is [K,N].
// VEC4: COMPILE-TIME float4 global loads for A (and B when TRANSB); K%4==0 required.
// SYMM: A==B, C symmetric, linear grid over lower-tri tiles, off-diag mirrored.
// Batched over blockIdx.z via zs* strides (size_t to allow 256MB sim stride).
template<bool TRANSB, bool BIAS_RELU, bool VEC4, bool SYMM>
__global__ __launch_bounds__(256) void gemm_bf16x3(const float* __restrict__ A,
                                                   const float* __restrict__ B,
                                                   const float* __restrict__ bias,
                                                   float* __restrict__ C,
                                                   int M, int N, int K,
                                                   size_t zsA, size_t zsB,
                                                   size_t zsBias, size_t zsC)
{
    __shared__ uint32_t sAhi[128 * SSTR];
    __shared__ uint32_t sAlo[128 * SSTR];
    __shared__ uint32_t sBhi[128 * SSTR];
    __shared__ uint32_t sBlo[128 * SSTR];

    A += (size_t)blockIdx.z * zsA;
    B += (size_t)blockIdx.z * zsB;
    if (BIAS_RELU) bias += (size_t)blockIdx.z * zsBias;
    C += (size_t)blockIdx.z * zsC;

    const int tid  = threadIdx.x;
    const int lane = tid & 31;
    const int warp = tid >> 5;
    const int gid  = lane >> 2;
    const int tig  = lane & 3;
    const int wm   = warp >> 2;     // 0..1 -> m offset wm*64
    const int wn   = warp & 3;      // 0..3 -> n offset wn*32

    int mo, no;
    bool mirror = false;
    if (SYMM) {
        int t = blockIdx.x;
        int bi = (int)((sqrtf(8.f * (float)t + 1.f) - 1.f) * 0.5f);
        while ((bi + 1) * (bi + 2) / 2 <= t) bi++;
        while (bi * (bi + 1) / 2 > t) bi--;
        int bj = t - bi * (bi + 1) / 2;
        mo = bi * 128; no = bj * 128;
        mirror = (bi != bj);
    } else {
        mo = blockIdx.y * 128;
        no = blockIdx.x * 128;
    }

    float acc[4][4][4];
#pragma unroll
    for (int i = 0; i < 4; i++)
#pragma unroll
        for (int j = 0; j < 4; j++)
#pragma unroll
            for (int q = 0; q < 4; q++) acc[i][j][q] = 0.f;

    // ldmatrix lane address components (bytes)
    const uint32_t aoff = (uint32_t)((wm * 64 + (lane & 7) + ((lane >> 3) & 1) * 8) * (SSTR * 4)
                                     + ((lane >> 4) & 1) * 16);
    const uint32_t boff = (uint32_t)((wn * 32 + (lane & 7) + ((lane >> 4) & 1) * 8) * (SSTR * 4)
                                     + ((lane >> 3) & 1) * 16);
    const uint32_t baseAhi = smem_u32(sAhi), baseAlo = smem_u32(sAlo);
    const uint32_t baseBhi = smem_u32(sBhi), baseBlo = smem_u32(sBlo);

    auto loadA = [&](int ko, int u) -> float4 {
        int f = u * 256 + tid;
        int r = f >> 3, kq = f & 7;
        int gk = ko + kq * 4;
        float4 v;
        if (VEC4 && gk + 3 < K) {
            v = *reinterpret_cast<const float4*>(&A[(size_t)(mo + r) * K + gk]);
        } else {
            const float* p = &A[(size_t)(mo + r) * K];
            v.x = (gk + 0 < K) ? p[gk + 0] : 0.f;
            v.y = (gk + 1 < K) ? p[gk + 1] : 0.f;
            v.z = (gk + 2 < K) ? p[gk + 2] : 0.f;
            v.w = (gk + 3 < K) ? p[gk + 3] : 0.f;
        }
        return v;
    };
    auto loadB = [&](int ko, int u) -> float4 {
        float4 v;
        if (TRANSB) {
            int f = u * 256 + tid;
            int r = f >> 3, kq = f & 7;
            int gk = ko + kq * 4;
            if (VEC4 && gk + 3 < K) {
                v = *reinterpret_cast<const float4*>(&B[(size_t)(no + r) * K + gk]);
            } else {
                const float* p = &B[(size_t)(no + r) * K];
                v.x = (gk + 0 < K) ? p[gk + 0] : 0.f;
                v.y = (gk + 1 < K) ? p[gk + 1] : 0.f;
                v.z = (gk + 2 < K) ? p[gk + 2] : 0.f;
                v.w = (gk + 3 < K) ? p[gk + 3] : 0.f;
            }
        } else {
            int f = u * 256 + tid;
            int n = f & 127;
            int kq = f >> 7;
            int gk = ko + kq * 4;
            v.x = (gk + 0 < K) ? B[(size_t)(gk + 0) * N + no + n] : 0.f;
            v.y = (gk + 1 < K) ? B[(size_t)(gk + 1) * N + no + n] : 0.f;
            v.z = (gk + 2 < K) ? B[(size_t)(gk + 2) * N + no + n] : 0.f;
            v.w = (gk + 3 < K) ? B[(size_t)(gk + 3) * N + no + n] : 0.f;
        }
        return v;
    };

    float4 va[4], vb[4];
#pragma unroll
    for (int u = 0; u < 4; u++) { va[u] = loadA(0, u); vb[u] = loadB(0, u); }

    for (int ko = 0; ko < K; ko += 32) {
#pragma unroll
        for (int u = 0; u < 4; u++) {
            int f = u * 256 + tid;
            uint32_t h0, h1, l0, l1;
            {   // A: [row][pair]
                int r = f >> 3, kq = f & 7;
                split4(va[u], h0, h1, l0, l1);
                int w = r * SSTR + kq * 2;
                sAhi[w] = h0; sAhi[w + 1] = h1;
                sAlo[w] = l0; sAlo[w + 1] = l1;
            }
            {   // B: [n][pair]
                int r, kq;
                if (TRANSB) { r = f >> 3; kq = f & 7; }
                else        { r = f & 127; kq = f >> 7; }
                split4(vb[u], h0, h1, l0, l1);
                int w = r * SSTR + kq * 2;
                sBhi[w] = h0; sBhi[w + 1] = h1;
                sBlo[w] = l0; sBlo[w + 1] = l1;
            }
        }
        __syncthreads();

        const int kn = ko + 32;
        if (kn < K) {
#pragma unroll
            for (int u = 0; u < 4; u++) { va[u] = loadA(kn, u); vb[u] = loadB(kn, u); }
        }

#pragma unroll
        for (int ks = 0; ks < 2; ks++) {
            const uint32_t kb = (uint32_t)(ks * 32);
            uint32_t bhi[4][2], blo[4][2];
#pragma unroll
            for (int p = 0; p < 2; p++) {
                LDSM_X4(bhi[2 * p][0], bhi[2 * p][1], bhi[2 * p + 1][0], bhi[2 * p + 1][1],
                        baseBhi + boff + (uint32_t)(p * 16 * SSTR * 4) + kb);
                LDSM_X4(blo[2 * p][0], blo[2 * p][1], blo[2 * p + 1][0], blo[2 * p + 1][1],
                        baseBlo + boff + (uint32_t)(p * 16 * SSTR * 4) + kb);
            }
#pragma unroll
            for (int i = 0; i < 4; i++) {
                uint32_t ahi[4], alo[4];
                LDSM_X4(ahi[0], ahi[1], ahi[2], ahi[3],
                        baseAhi + aoff + (uint32_t)(i * 16 * SSTR * 4) + kb);
                LDSM_X4(alo[0], alo[1], alo[2], alo[3],
                        baseAlo + aoff + (uint32_t)(i * 16 * SSTR * 4) + kb);
#pragma unroll
                for (int j = 0; j < 4; j++) {
                    MMA_BF16(acc[i][j], ahi, bhi[j]);
                    MMA_BF16(acc[i][j], ahi, blo[j]);
                    MMA_BF16(acc[i][j], alo, bhi[j]);
                }
            }
        }
        __syncthreads();
    }

    // ---- epilogue
#pragma unroll
    for (int i = 0; i < 4; i++) {
        const int r0 = mo + wm * 64 + i * 16 + gid;
#pragma unroll
        for (int j = 0; j < 4; j++) {
            const int c = no + wn * 32 + j * 8 + tig * 2;
            float v0 = acc[i][j][0], v1 = acc[i][j][1];
            float v2 = acc[i][j][2], v3 = acc[i][j][3];
            if (BIAS_RELU) {
                const float b0 = bias[c], b1 = bias[c + 1];
                v0 = fmaxf(v0 + b0, 0.f); v1 = fmaxf(v1 + b1, 0.f);
                v2 = fmaxf(v2 + b0, 0.f); v3 = fmaxf(v3 + b1, 0.f);
            }
            *reinterpret_cast<float2*>(&C[(size_t)r0 * N + c])       = make_float2(v0, v1);
            *reinterpret_cast<float2*>(&C[(size_t)(r0 + 8) * N + c]) = make_float2(v2, v3);
            if (SYMM && mirror) {
                C[(size_t)c * N + r0]           = v0;
                C[(size_t)(c + 1) * N + r0]     = v1;
                C[(size_t)c * N + r0 + 8]       = v2;
                C[(size_t)(c + 1) * N + r0 + 8] = v3;
            }
        }
    }
}

// ---------------- BatchNorm stats (two stage, deterministic, z-batched) ----------
__global__ void bn_colpart(void)
{
    const int z = blockIdx.z;
    const float* t = g_t + (size_t)z * NH;
    float* part = g_part + (size_t)z * 2 * 64 * HID;
    const int c = threadIdx.x;
    const int r0 = blockIdx.x * 128;
    float s = 0.f, s2 = 0.f;
    for (int r = r0; r < r0 + 128; r++) {
        float v = t[(size_t)r * HID + c];
        s += v; s2 += v * v;
    }
    part[blockIdx.x * HID + c] = s;
    part[64 * HID + blockIdx.x * HID + c] = s2;
}

__global__ void bn_colfinal(const float* __restrict__ gam, const float* __restrict__ bet)
{
    const int z = blockIdx.z;
    const float* part = g_part + (size_t)z * 2 * 64 * HID;
    const int c = threadIdx.x;
    float s = 0.f, s2 = 0.f;
    for (int b = 0; b < 64; b++) {
        s  += part[b * HID + c];
        s2 += part[64 * HID + b * HID + c];
    }
    const float mu = s * (1.f / N_NODES);
    float var = s2 * (1.f / N_NODES) - mu * mu;
    const float a = gam[z * HID + c] * rsqrtf(var + 1e-5f);
    g_bna[z * HID + c] = a;
    g_bnc[z * HID + c] = bet[z * HID + c] - mu * a;
}

__global__ __launch_bounds__(256) void bn_apply_rownorm(void)
{
    const int z = blockIdx.z;
    const float* t = g_t + (size_t)z * NH;
    float* feat = g_feat + (size_t)z * NH;
    float* fn   = g_fn   + (size_t)z * NH;
    const int tid = threadIdx.x;
    const int warp = tid >> 5, lane = tid & 31;
    const int row = blockIdx.x * 8 + warp;
    float v[8];
    float sq = 0.f;
#pragma unroll
    for (int u = 0; u < 8; u++) {
        int c = lane + 32 * u;
        float x = g_bna[z * HID + c] * t[(size_t)row * HID + c] + g_bnc[z * HID + c];
        v[u] = x; sq += x * x;
    }
#pragma unroll
    for (int s = 16; s; s >>= 1) sq += __shfl_xor_sync(0xffffffffu, sq, s);
    const float norm = sqrtf(sq);
    const float inv = 1.f / fmaxf(norm, 1e-12f);
#pragma unroll
    for (int u = 0; u < 8; u++) {
        int c = lane + 32 * u;
        feat[(size_t)row * HID + c] = v[u];
        fn[(size_t)row * HID + c]   = v[u] * inv;
    }
}

// ---------------- top-(K+1) per row + sparse adjacency build (z-batched) ----------
// R7 tree-merge + R11 float4 scan, per-modality sim buffer via blockIdx.z.
__global__ __launch_bounds__(256) void topk_adj(void)
{
    const int z   = blockIdx.z;
    const int row = blockIdx.x;
    const int tid = threadIdx.x;
    const float* __restrict__ srow = g_sim + (size_t)z * NN + (size_t)row * N_NODES;
    int*   aidx = g_adj_idx + (size_t)z * N_NODES * TOPK;
    float* aw   = g_adj_w   + (size_t)z * N_NODES * TOPK;

    float lv[TOPK]; int li[TOPK];
#pragma unroll
    for (int k = 0; k < TOPK; k++) { lv[k] = -FLT_MAX; li[k] = 0x7FFFFFFF; }

    auto insert = [&](float v, int j) {
        if (v > lv[TOPK - 1]) {
            lv[TOPK - 1] = v; li[TOPK - 1] = j;
#pragma unroll
            for (int k = TOPK - 1; k > 0; k--) {
                if (lv[k] > lv[k - 1]) {
                    float tv = lv[k]; lv[k] = lv[k - 1]; lv[k - 1] = tv;
                    int   ti = li[k]; li[k] = li[k - 1]; li[k - 1] = ti;
                } else break;
            }
        }
    };

    for (int j4 = tid * 4; j4 < N_NODES; j4 += 1024) {
        float4 v4 = *reinterpret_cast<const float4*>(&srow[j4]);
        insert(v4.x, j4 + 0);
        insert(v4.y, j4 + 1);
        insert(v4.z, j4 + 2);
        insert(v4.w, j4 + 3);
    }

    __shared__ float cv[256 * TOPK];
    __shared__ int   ci[256 * TOPK];
#pragma unroll
    for (int k = 0; k < TOPK; k++) { cv[tid * TOPK + k] = lv[k]; ci[tid * TOPK + k] = li[k]; }

    __shared__ float rv[256];
    __shared__ int   ri[256];
    __shared__ float topv[TOPK];
    __shared__ int   topi[TOPK];

    int p = 0;
    for (int r = 0; r < TOPK; r++) {
        float mv = (p < TOPK) ? cv[tid * TOPK + p] : -FLT_MAX;
        int   mj = (p < TOPK) ? ci[tid * TOPK + p] : 0x7FFFFFFF;
        rv[tid] = mv; ri[tid] = mj;
        __syncthreads();
        for (int s = 128; s > 0; s >>= 1) {
            if (tid < s) {
                float ov = rv[tid + s]; int oj = ri[tid + s];
                if (ov > rv[tid] || (ov == rv[tid] && oj < ri[tid])) { rv[tid] = ov; ri[tid] = oj; }
            }
            __syncthreads();
        }
        int bj = ri[0];
        if (tid == 0) { topv[r] = rv[0]; topi[r] = bj; }
        if (mj == bj) p++;           // j unique per candidate -> winner advances
        __syncthreads();
    }

    if (tid == 0) {
        float diag = 1.0f;
        float wv[TOPK]; int wi[TOPK]; int cnt = 0;
        for (int k = 1; k < TOPK; k++) {
            if (topi[k] == row) diag += topv[k];
            else { wv[cnt] = topv[k]; wi[cnt] = topi[k]; cnt++; }
        }
        float rs = fabsf(diag);
        for (int k = 0; k < cnt; k++) rs += fabsf(wv[k]);
        rs = fmaxf(rs, 1e-12f);
        const float inv = 1.f / rs;
        aidx[row * TOPK + 0] = row;
        aw[row * TOPK + 0]   = diag * inv;
        for (int k = 0; k < cnt; k++) {
            aidx[row * TOPK + 1 + k] = wi[k];
            aw[row * TOPK + 1 + k]   = wv[k] * inv;
        }
        for (int k = cnt; k < TOPK - 1; k++) {
            aidx[row * TOPK + 1 + k] = row;
            aw[row * TOPK + 1 + k]   = 0.f;
        }
    }
}

// ---------------- sparse adj @ t + bias, leaky(0.25)  (z-batched) ----------------
__global__ void spmm_leaky(const float* __restrict__ t,
                           const float* __restrict__ bias,
                           float* __restrict__ out)
{
    const int z = blockIdx.z;
    const float* tz = t + (size_t)z * NH;
    const float* bz = bias + (size_t)z * HID;
    float* oz = out + (size_t)z * NH;
    const int* ai = g_adj_idx + (size_t)z * N_NODES * TOPK;
    const float* aw = g_adj_w + (size_t)z * N_NODES * TOPK;

    const int row = blockIdx.x;
    const int c = threadIdx.x;
    float acc = bz[c];
#pragma unroll
    for (int k = 0; k < TOPK; k++) {
        int   j = ai[row * TOPK + k];
        float w = aw[row * TOPK + k];
        acc += w * tz[(size_t)j * HID + c];
    }
    oz[(size_t)row * HID + c] = (acc >= 0.f) ? acc : 0.25f * acc;
}

// ---------------- classifier (z-batched): logits = h @ W[256,5] + b --------------
__global__ __launch_bounds__(256) void clf_kernel(const float* __restrict__ h,
                                                  const float* __restrict__ W,
                                                  const float* __restrict__ b)
{
    const int z = blockIdx.z;
    const float* hz = h + (size_t)z * NH;
    const float* Wz = W + (size_t)z * HID * NCLS;
    const float* bz = b + (size_t)z * NCLS;
    float* oz = g_logits + (size_t)z * N_NODES * NCLS;

    __shared__ float Ws[HID * NCLS];
    const int tid = threadIdx.x;
    for (int i = tid; i < HID * NCLS; i += 256) Ws[i] = Wz[i];
    __syncthreads();
    const int warp = tid >> 5, lane = tid & 31;
    const int row = blockIdx.x * 8 + warp;
    float hv[8];
#pragma unroll
    for (int u = 0; u < 8; u++) hv[u] = hz[(size_t)row * HID + lane + 32 * u];
#pragma unroll
    for (int c = 0; c < NCLS; c++) {
        float acc = 0.f;
#pragma unroll
        for (int u = 0; u < 8; u++) acc += hv[u] * Ws[(lane + 32 * u) * NCLS + c];
#pragma unroll
        for (int s = 16; s; s >>= 1) acc += __shfl_down_sync(0xffffffffu, acc, s);
        if (lane == 0) oz[row * NCLS + c] = acc + bz[c];
    }
}

// ---------------- fusion: softmax(attn), sigmoid mix, 5->128->5 MLP ----------------
__global__ __launch_bounds__(256) void fusion_kernel(const float* __restrict__ attn,
                                                     const float* __restrict__ f1W,
                                                     const float* __restrict__ f1b,
                                                     const float* __restrict__ f2W,
                                                     const float* __restrict__ f2b,
                                                     float* __restrict__ out)
{
    __shared__ float s1[NCLS * 128];
    __shared__ float s2[128 * NCLS];
    __shared__ float sb1[128];
    __shared__ float sb2[NCLS];
    const int tid = threadIdx.x;
    for (int i = tid; i < NCLS * 128; i += 256) s1[i] = f1W[i];
    for (int i = tid; i < 128 * NCLS; i += 256) s2[i] = f2W[i];
    if (tid < 128) sb1[tid] = f1b[tid];
    if (tid < NCLS) sb2[tid] = f2b[tid];
    __syncthreads();

    const int row = blockIdx.x * 256 + tid;
    const float a0 = attn[0], a1 = attn[1], a2 = attn[2];
    const float m = fmaxf(a0, fmaxf(a1, a2));
    const float e0 = expf(a0 - m), e1 = expf(a1 - m), e2 = expf(a2 - m);
    const float invs = 1.f / (e0 + e1 + e2);
    const float w0 = e0 * invs, w1 = e1 * invs, w2 = e2 * invs;

    float fused[NCLS];
#pragma unroll
    for (int c = 0; c < NCLS; c++) {
        float l0 = g_logits[0 * N_NODES * NCLS + row * NCLS + c];
        float l1 = g_logits[1 * N_NODES * NCLS + row * NCLS + c];
        float l2 = g_logits[2 * N_NODES * NCLS + row * NCLS + c];
        fused[c] = w0 / (1.f + expf(-l0)) + w1 / (1.f + expf(-l1)) + w2 / (1.f + expf(-l2));
    }
    float o[NCLS];
#pragma unroll
    for (int c = 0; c < NCLS; c++) o[c] = sb2[c];
    for (int j = 0; j < 128; j++) {
        float t = sb1[j];
#pragma unroll
        for (int c = 0; c < NCLS; c++) t += fused[c] * s1[c * 128 + j];
        t = (t >= 0.f) ? t : 0.25f * t;
#pragma unroll
        for (int c = 0; c < NCLS; c++) o[c] += t * s2[j * NCLS + c];
    }
#pragma unroll
    for (int c = 0; c < NCLS; c++) out[(size_t)row * NCLS + c] = o[c];
}

// ---------------- host launcher ----------------
extern "C" void kernel_launch(void* const* d_in, const int* in_sizes, int n_in,
                              void* d_out, int out_size)
{
    (void)n_in; (void)out_size;
    const float* x[3]    = {(const float*)d_in[0], (const float*)d_in[1], (const float*)d_in[2]};
    const float* encW[3] = {(const float*)d_in[3], (const float*)d_in[4], (const float*)d_in[5]};
    const float* enc_b = (const float*)d_in[6];
    const float* bn_g  = (const float*)d_in[7];
    const float* bn_b  = (const float*)d_in[8];
    const float* gc1W  = (const float*)d_in[9];
    const float* gc1b  = (const float*)d_in[10];
    const float* gc2W  = (const float*)d_in[11];
    const float* gc2b  = (const float*)d_in[12];
    const float* clfW  = (const float*)d_in[13];
    const float* clfb  = (const float*)d_in[14];
    const float* attn  = (const float*)d_in[15];
    const float* f1W   = (const float*)d_in[16];
    const float* f1b   = (const float*)d_in[17];
    const float* f2W   = (const float*)d_in[18];
    const float* f2b   = (const float*)d_in[19];

    float *p_sim, *p_t, *p_feat, *p_fn, *p_h;
    cudaGetSymbolAddress((void**)&p_sim,  g_sim);
    cudaGetSymbolAddress((void**)&p_t,    g_t);
    cudaGetSymbolAddress((void**)&p_feat, g_feat);
    cudaGetSymbolAddress((void**)&p_fn,   g_fn);
    cudaGetSymbolAddress((void**)&p_h,    g_h);

    const int NTILE = N_NODES / 128;
    const int NSYMM = NTILE * (NTILE + 1) / 2;   // 2080

    // ---- encoders (separate launches, compile-time VEC4 selection) ----
    for (int i = 0; i < 3; i++) {
        const int Kenc = in_sizes[i] / N_NODES;
        dim3 grid(HID / 128, N_NODES / 128, 1);
        if ((Kenc & 3) == 0)
            gemm_bf16x3<false, true, true, false><<<grid, 256>>>(x[i], encW[i], enc_b + i * HID,
                p_t + (size_t)i * NH, N_NODES, HID, Kenc, 0, 0, 0, 0);
        else
            gemm_bf16x3<false, true, false, false><<<grid, 256>>>(x[i], encW[i], enc_b + i * HID,
                p_t + (size_t)i * NH, N_NODES, HID, Kenc, 0, 0, 0, 0);
    }

    // ---- batchnorm + rownorm (batched over z) ----
    bn_colpart<<<dim3(64, 1, 3), 256>>>();
    bn_colfinal<<<dim3(1, 1, 3), 256>>>(bn_g, bn_b);
    bn_apply_rownorm<<<dim3(N_NODES / 8, 1, 3), 256>>>();

    // ---- sim (symmetric, ALL modalities in one z=3 launch) + topk (z=3) ----
    gemm_bf16x3<true, false, true, true><<<dim3(NSYMM, 1, 3), 256>>>(
        p_fn, p_fn, nullptr, p_sim, N_NODES, N_NODES, HID,
        (size_t)NH, (size_t)NH, 0, NN);
    topk_adj<<<dim3(N_NODES, 1, 3), 256>>>();

    // ---- GCN layers (batched z=3) ----
    {
        dim3 grid(HID / 128, N_NODES / 128, 3);
        gemm_bf16x3<false, false, true, false><<<grid, 256>>>(p_feat, gc1W, nullptr, p_t,
            N_NODES, HID, HID, (size_t)NH, (size_t)(HID * HID), 0, (size_t)NH);
        spmm_leaky<<<dim3(N_NODES, 1, 3), HID>>>(p_t, gc1b, p_h);
        gemm_bf16x3<false, false, true, false><<<grid, 256>>>(p_h, gc2W, nullptr, p_t,
            N_NODES, HID, HID, (size_t)NH, (size_t)(HID * HID), 0, (size_t)NH);
        spmm_leaky<<<dim3(N_NODES, 1, 3), HID>>>(p_t, gc2b, p_h);
    }

    // ---- classifier (batched) + fusion ----
    clf_kernel<<<dim3(N_NODES / 8, 1, 3), 256>>>(p_h, clfW, clfb);
    fusion_kernel<<<N_NODES / 256, 256>>>(attn, f1W, f1b, f2W, f2b, (float*)d_out);
}